// round 16
// baseline (speedup 1.0000x reference)
#include <cuda_runtime.h>
#include <cuda_fp16.h>
#include <math.h>
#include <stdint.h>

// Problem constants
#define BN_ 8
#define TN_ 1024
#define CN_ 1024
#define HN_ 16
#define DH_ 64
#define MD_ (BN_ * TN_)      // 8192 rows
#define FFD_ (4 * CN_)       // 4096

// ---------------------------------------------------------------------------
// Scratch (device globals — no allocation allowed)
// ---------------------------------------------------------------------------
__device__ __half g_h  [MD_ * CN_];
__device__ __half g_q  [MD_ * CN_];
__device__ __half g_k  [MD_ * CN_];
__device__ __half g_v  [MD_ * CN_];
__device__ __half g_ctx[MD_ * CN_];
__device__ float  g_x1 [MD_ * CN_];
__device__ __half g_h2 [MD_ * CN_];
__device__ __half g_ff [MD_ * FFD_];
// transposed half weights: Wt[n][k] = W[k][n]
__device__ __half g_wqt[CN_ * CN_];
__device__ __half g_wkt[CN_ * CN_];
__device__ __half g_wvt[CN_ * CN_];
__device__ __half g_wot[CN_ * CN_];
__device__ __half g_w1t[FFD_ * CN_];
__device__ __half g_w2t[CN_ * FFD_];

// ---------------------------------------------------------------------------
// Helpers
// ---------------------------------------------------------------------------
__device__ __forceinline__ uint32_t smem_u32(const void* p) {
    uint32_t a;
    asm("{ .reg .u64 t; cvta.to.shared.u64 t, %1; cvt.u32.u64 %0, t; }" : "=r"(a) : "l"(p));
    return a;
}
__device__ __forceinline__ void cp_async16(uint32_t dst, const void* src) {
    asm volatile("cp.async.cg.shared.global [%0], [%1], 16;" :: "r"(dst), "l"(src));
}
__device__ __forceinline__ void cp_commit() {
    asm volatile("cp.async.commit_group;" ::: "memory");
}
__device__ __forceinline__ void cp_wait0() {
    asm volatile("cp.async.wait_group 0;" ::: "memory");
}
__device__ __forceinline__ void cp_wait1() {
    asm volatile("cp.async.wait_group 1;" ::: "memory");
}

__device__ __forceinline__ void mma_f16(float* d, const uint32_t* a,
                                        uint32_t b0, uint32_t b1)
{
    asm volatile(
        "mma.sync.aligned.m16n8k16.row.col.f32.f16.f16.f32 "
        "{%0,%1,%2,%3}, {%4,%5,%6,%7}, {%8,%9}, {%0,%1,%2,%3};"
        : "+f"(d[0]), "+f"(d[1]), "+f"(d[2]), "+f"(d[3])
        : "r"(a[0]), "r"(a[1]), "r"(a[2]), "r"(a[3]), "r"(b0), "r"(b1));
}
__device__ __forceinline__ void ldsm_x4(uint32_t* r, uint32_t addr)
{
    asm volatile("ldmatrix.sync.aligned.m8n8.x4.shared.b16 {%0,%1,%2,%3}, [%4];"
                 : "=r"(r[0]), "=r"(r[1]), "=r"(r[2]), "=r"(r[3]) : "r"(addr));
}
__device__ __forceinline__ void ldsm_x2_t(uint32_t& r0, uint32_t& r1, uint32_t addr)
{
    asm volatile("ldmatrix.sync.aligned.m8n8.x2.trans.shared.b16 {%0,%1}, [%2];"
                 : "=r"(r0), "=r"(r1) : "r"(addr));
}
__device__ __forceinline__ uint32_t packh2(float a, float b)
{
    const __half2 h = __floats2half2_rn(a, b);
    return *reinterpret_cast<const uint32_t*>(&h);
}

__device__ __forceinline__ float gelu_exact(float x)
{
    return 0.5f * x * (1.0f + erff(x * 0.70710678118654752f));
}

// ---------------------------------------------------------------------------
// Transpose + convert: Wt[n][k] = half(W[k][n]).
// Tile 64(k) x 32(n); block 32x8. Stores are half2 (aligned 4B per lane).
// ---------------------------------------------------------------------------
__global__ __launch_bounds__(256)
void convt(const float* W0, const float* W1, const float* W2, const float* W3,
           __half* T0, __half* T1, __half* T2, __half* T3, int K, int N)
{
    const int z = blockIdx.z;
    const float* W = (z == 0) ? W0 : (z == 1) ? W1 : (z == 2) ? W2 : W3;
    __half*      T = (z == 0) ? T0 : (z == 1) ? T1 : (z == 2) ? T2 : T3;

    __shared__ float tile[64][33];
    const int tx = threadIdx.x, ty = threadIdx.y;
    const int n0 = blockIdx.x * 32, k0 = blockIdx.y * 64;
    #pragma unroll
    for (int j = 0; j < 64; j += 8)
        tile[ty + j][tx] = W[(size_t)(k0 + ty + j) * N + n0 + tx];
    __syncthreads();
    #pragma unroll
    for (int j = 0; j < 32; j += 8) {
        const int n = n0 + ty + j;
        const __half2 hv = __floats2half2_rn(tile[2 * tx][ty + j],
                                             tile[2 * tx + 1][ty + j]);
        *(__half2*)(T + (size_t)n * K + k0 + 2 * tx) = hv;
    }
}

// ---------------------------------------------------------------------------
// FP16 tensor-core GEMM (R8 known-good): C = A@W + bias (+gelu)(+res).
// 128x128 tile, BK=32, 256 threads (8 warps 4x2, warp tile 32x64).
// 3-stage cp.async pipeline. ldmatrix.x4 fragments, stride 40 halves.
// ---------------------------------------------------------------------------
#define SG_STR 40
#define SG_TILE (128 * SG_STR)
#define SMEM_GEMM_BYTES (3 * 2 * SG_TILE * 2)  // 61440 B

__global__ __launch_bounds__(256, 2)
void gemm_h(const __half* __restrict__ A,
            const __half* T0, const __half* T1, const __half* T2,
            const float* b0p, const float* b1p, const float* b2p,
            __half* h0p, __half* h1p, __half* h2p,
            float* of, const float* __restrict__ res,
            int M, int N, int K, int act)
{
    const int z = blockIdx.z;
    const __half* Wt   = (z == 0) ? T0  : (z == 1) ? T1  : T2;
    const float*  bias = (z == 0) ? b0p : (z == 1) ? b1p : b2p;
    __half*       Ch   = (z == 0) ? h0p : (z == 1) ? h1p : h2p;

    extern __shared__ __half smh[];
    __half* sA0 = smh;
    const uint32_t sA_u[3] = { smem_u32(sA0),
                               smem_u32(sA0 + 2 * SG_TILE),
                               smem_u32(sA0 + 4 * SG_TILE) };
    const uint32_t sB_u[3] = { smem_u32(sA0 + SG_TILE),
                               smem_u32(sA0 + 3 * SG_TILE),
                               smem_u32(sA0 + 5 * SG_TILE) };

    const int tid  = threadIdx.x;
    const int wid  = tid >> 5;
    const int lane = tid & 31;
    const int g    = lane >> 2;
    const int tq   = lane & 3;
    const int bm = blockIdx.y * 128;
    const int bn = blockIdx.x * 128;
    const int wm = (wid & 3) * 32;
    const int wn = (wid >> 2) * 64;

    const uint32_t offA0 = (uint32_t)(((wm + (lane & 15)) * SG_STR + (lane >> 4) * 8) * 2);
    const uint32_t offA1 = offA0 + 16u * SG_STR * 2u;
    const int rB = (lane & 7) + ((lane >> 4) & 1) * 8;
    const uint32_t cBo = (uint32_t)(((lane >> 3) & 1) * 8);
    uint32_t offB[4];
    #pragma unroll
    for (int n2 = 0; n2 < 4; n2++)
        offB[n2] = (uint32_t)(((wn + n2 * 16 + rB) * SG_STR + cBo) * 2);

    float acc[2][8][4];
    #pragma unroll
    for (int ms = 0; ms < 2; ms++)
        #pragma unroll
        for (int ns = 0; ns < 8; ns++)
            #pragma unroll
            for (int i = 0; i < 4; i++) acc[ms][ns][i] = 0.f;

    const int nChunks = K >> 5;

    auto loadAB = [&](int c, int b) {
        const __half* Ab = A + (size_t)bm * K + (c << 5);
        const __half* Bb = Wt + (size_t)bn * K + (c << 5);
        #pragma unroll
        for (int it = 0; it < 2; ++it) {
            const int idx = tid + it * 256;
            const int row = idx >> 2;
            const int seg = idx & 3;
            cp_async16(sA_u[b] + (uint32_t)(row * SG_STR * 2 + seg * 16),
                       Ab + (size_t)row * K + seg * 8);
            cp_async16(sB_u[b] + (uint32_t)(row * SG_STR * 2 + seg * 16),
                       Bb + (size_t)row * K + seg * 8);
        }
    };

    auto compute = [&](int b) {
        const uint32_t bA = sA_u[b];
        const uint32_t bB = sB_u[b];
        #pragma unroll
        for (int kk = 0; kk < 2; kk++) {
            const uint32_t ko = (uint32_t)(kk * 32);
            uint32_t a[2][4];
            ldsm_x4(a[0], bA + offA0 + ko);
            ldsm_x4(a[1], bA + offA1 + ko);
            #pragma unroll
            for (int n2 = 0; n2 < 4; n2++) {
                uint32_t bb[4];
                ldsm_x4(bb, bB + offB[n2] + ko);
                mma_f16(acc[0][2 * n2],     a[0], bb[0], bb[1]);
                mma_f16(acc[1][2 * n2],     a[1], bb[0], bb[1]);
                mma_f16(acc[0][2 * n2 + 1], a[0], bb[2], bb[3]);
                mma_f16(acc[1][2 * n2 + 1], a[1], bb[2], bb[3]);
            }
        }
    };

    loadAB(0, 0); cp_commit();
    if (nChunks > 1) { loadAB(1, 1); cp_commit(); }

    for (int c = 0; c < nChunks; ++c) {
        if (c + 1 < nChunks) cp_wait1(); else cp_wait0();
        __syncthreads();
        compute(c % 3);
        if (c + 2 < nChunks) { loadAB(c + 2, (c + 2) % 3); cp_commit(); }
    }

    #pragma unroll
    for (int ms = 0; ms < 2; ms++) {
        const int r0 = bm + wm + 16 * ms + g;
        const int r1 = r0 + 8;
        #pragma unroll
        for (int ns = 0; ns < 8; ns++) {
            const int col = bn + wn + 8 * ns + 2 * tq;
            const float2 bb = *(const float2*)(bias + col);
            float o00 = acc[ms][ns][0] + bb.x;
            float o01 = acc[ms][ns][1] + bb.y;
            float o10 = acc[ms][ns][2] + bb.x;
            float o11 = acc[ms][ns][3] + bb.y;
            if (act) {
                o00 = gelu_exact(o00); o01 = gelu_exact(o01);
                o10 = gelu_exact(o10); o11 = gelu_exact(o11);
            }
            if (of) {
                if (res) {
                    const float2 q0 = *(const float2*)(res + (size_t)r0 * N + col);
                    const float2 q1 = *(const float2*)(res + (size_t)r1 * N + col);
                    o00 += q0.x; o01 += q0.y; o10 += q1.x; o11 += q1.y;
                }
                *(float2*)(of + (size_t)r0 * N + col) = make_float2(o00, o01);
                *(float2*)(of + (size_t)r1 * N + col) = make_float2(o10, o11);
            } else {
                *(__half2*)(Ch + (size_t)r0 * N + col) = __floats2half2_rn(o00, o01);
                *(__half2*)(Ch + (size_t)r1 * N + col) = __floats2half2_rn(o10, o11);
            }
        }
    }
}

// ---------------------------------------------------------------------------
// LayerNorm: warp-per-row, 8 rows per block (grid 1024). No smem, no barrier.
// ---------------------------------------------------------------------------
__global__ __launch_bounds__(256)
void ln_kernel(const float* __restrict__ x, const float* __restrict__ w,
               const float* __restrict__ b, __half* __restrict__ out)
{
    const int wid  = threadIdx.x >> 5;
    const int lane = threadIdx.x & 31;
    const int row  = blockIdx.x * 8 + wid;

    const float* xr = x + (size_t)row * CN_;
    float4 v[8];
    float s = 0.f, ss = 0.f;
    #pragma unroll
    for (int i = 0; i < 8; i++) {
        v[i] = *(const float4*)(xr + (i * 32 + lane) * 4);
        s  += v[i].x + v[i].y + v[i].z + v[i].w;
        ss += v[i].x * v[i].x + v[i].y * v[i].y
            + v[i].z * v[i].z + v[i].w * v[i].w;
    }
    #pragma unroll
    for (int o = 16; o > 0; o >>= 1) {
        s  += __shfl_xor_sync(0xFFFFFFFFu, s,  o);
        ss += __shfl_xor_sync(0xFFFFFFFFu, ss, o);
    }

    const float mu   = s * (1.0f / (float)CN_);
    const float var  = ss * (1.0f / (float)CN_) - mu * mu;
    const float rsig = rsqrtf(var + 1e-5f);

    __half* outr = out + (size_t)row * CN_;
    #pragma unroll
    for (int i = 0; i < 8; i++) {
        const int c = (i * 32 + lane) * 4;
        const float4 wv = *(const float4*)(w + c);
        const float4 bv = *(const float4*)(b + c);
        const float o0 = (v[i].x - mu) * rsig * wv.x + bv.x;
        const float o1 = (v[i].y - mu) * rsig * wv.y + bv.y;
        const float o2 = (v[i].z - mu) * rsig * wv.z + bv.z;
        const float o3 = (v[i].w - mu) * rsig * wv.w + bv.w;
        __half2 h01 = __floats2half2_rn(o0, o1);
        __half2 h23 = __floats2half2_rn(o2, o3);
        uint2 pk;
        pk.x = *reinterpret_cast<uint32_t*>(&h01);
        pk.y = *reinterpret_cast<uint32_t*>(&h23);
        *(uint2*)(outr + c) = pk;
    }
}

// ---------------------------------------------------------------------------
// FP16 flash attention (causal). Block 256 threads (8 warps); q-tile 128,
// kv-tile 64, d=64. Q frags in regs; P in registers.
// LPT scheduling: qt = (gridDim.x-1) - blockIdx.x so heaviest blocks first.
// ---------------------------------------------------------------------------
#define AT_STR 72
#define AQ_TILE (128 * AT_STR)
#define AKV_TILE (64 * AT_STR)
#define SMEM_ATTN_BYTES ((AQ_TILE + 4 * AKV_TILE) * 2)   // 55296 B

__global__ __launch_bounds__(256, 2)
void attn_tc(const __half* __restrict__ q, const __half* __restrict__ k,
             const __half* __restrict__ v, __half* __restrict__ out)
{
    extern __shared__ __half smh[];
    __half* sQ = smh;
    const uint32_t sQ_u    = smem_u32(sQ);
    const uint32_t sK_u[2] = { smem_u32(smh + AQ_TILE),
                               smem_u32(smh + AQ_TILE + 2 * AKV_TILE) };
    const uint32_t sV_u[2] = { smem_u32(smh + AQ_TILE + AKV_TILE),
                               smem_u32(smh + AQ_TILE + 3 * AKV_TILE) };

    const int qt  = (int)(gridDim.x - 1u) - blockIdx.x;   // heaviest first
    const int bh  = blockIdx.y;
    const int b   = bh >> 4;
    const int h   = bh & 15;
    const int tid  = threadIdx.x;
    const int wid  = tid >> 5;
    const int lane = tid & 31;
    const int g    = lane >> 2;
    const int tq   = lane & 3;

    const size_t headoff = (size_t)h * DH_;
    const __half* qbase = q + ((size_t)b * TN_ + qt * 128) * CN_ + headoff;

    #pragma unroll
    for (int it = 0; it < 4; ++it) {
        const int idx = tid + it * 256;
        const int row = idx >> 3;
        const int seg = idx & 7;
        cp_async16(sQ_u + (uint32_t)(row * AT_STR * 2 + seg * 16),
                   qbase + (size_t)row * CN_ + seg * 8);
    }
    auto loadKV = [&](int kt, int bb) {
        const __half* kb = k + ((size_t)b * TN_ + kt * 64) * CN_ + headoff;
        const __half* vb = v + ((size_t)b * TN_ + kt * 64) * CN_ + headoff;
        #pragma unroll
        for (int it = 0; it < 2; ++it) {
            const int idx = tid + it * 256;
            const int row = idx >> 3;
            const int seg = idx & 7;
            cp_async16(sK_u[bb] + (uint32_t)(row * AT_STR * 2 + seg * 16),
                       kb + (size_t)row * CN_ + seg * 8);
            cp_async16(sV_u[bb] + (uint32_t)(row * AT_STR * 2 + seg * 16),
                       vb + (size_t)row * CN_ + seg * 8);
        }
    };

    loadKV(0, 0);
    cp_commit();
    cp_wait0();
    __syncthreads();

    const int r_in0 = 16 * wid + g;
    const int r_in1 = r_in0 + 8;
    const int rowg0 = qt * 128 + r_in0;
    const int rowg1 = rowg0 + 8;

    const int rB = (lane & 7) + ((lane >> 4) & 1) * 8;
    const uint32_t cBo = (uint32_t)(((lane >> 3) & 1) * 8);
    uint32_t offK[4];
    #pragma unroll
    for (int n2 = 0; n2 < 4; n2++)
        offK[n2] = (uint32_t)(((n2 * 16 + rB) * AT_STR + cBo) * 2);

    uint32_t qa[4][4];
    {
        const __half2 sc = __float2half2_rn(0.125f);
        #pragma unroll
        for (int kk = 0; kk < 4; kk++) {
            const int kb = kk * 16 + 2 * tq;
            #pragma unroll
            for (int i = 0; i < 4; i++) {
                const int rr = (i & 1) ? r_in1 : r_in0;
                const int cc = kb + ((i >> 1) ? 8 : 0);
                uint32_t raw = *(const uint32_t*)(sQ + rr * AT_STR + cc);
                __half2 hv = *reinterpret_cast<__half2*>(&raw);
                hv = __hmul2(hv, sc);
                qa[kk][i] = *reinterpret_cast<uint32_t*>(&hv);
            }
        }
    }

    float o[8][4];
    #pragma unroll
    for (int ns = 0; ns < 8; ns++)
        #pragma unroll
        for (int i = 0; i < 4; i++) o[ns][i] = 0.f;
    float m0 = -1e30f, m1 = -1e30f, l0 = 0.f, l1 = 0.f;

    const int ktMax = 2 * qt + 1;

    for (int kt = 0; kt <= ktMax; kt++) {
        const int cur = kt & 1;
        if (kt + 1 <= ktMax) { loadKV(kt + 1, cur ^ 1); cp_commit(); }
        if (kt + 1 <= ktMax) cp_wait1(); else cp_wait0();
        __syncthreads();

        float s[8][4];
        #pragma unroll
        for (int ns = 0; ns < 8; ns++)
            #pragma unroll
            for (int i = 0; i < 4; i++) s[ns][i] = 0.f;
        #pragma unroll
        for (int kk = 0; kk < 4; kk++) {
            const uint32_t ko = (uint32_t)(kk * 32);
            #pragma unroll
            for (int n2 = 0; n2 < 4; n2++) {
                uint32_t bb[4];
                ldsm_x4(bb, sK_u[cur] + offK[n2] + ko);
                mma_f16(s[2 * n2],     qa[kk], bb[0], bb[1]);
                mma_f16(s[2 * n2 + 1], qa[kk], bb[2], bb[3]);
            }
        }

        if (kt >= 2 * qt) {
            const int colbase = kt * 64;
            #pragma unroll
            for (int ns = 0; ns < 8; ns++) {
                const int c0 = colbase + 8 * ns + 2 * tq;
                if (c0     > rowg0) s[ns][0] = -1e30f;
                if (c0 + 1 > rowg0) s[ns][1] = -1e30f;
                if (c0     > rowg1) s[ns][2] = -1e30f;
                if (c0 + 1 > rowg1) s[ns][3] = -1e30f;
            }
        }

        float rm0 = -1e30f, rm1 = -1e30f;
        #pragma unroll
        for (int ns = 0; ns < 8; ns++) {
            rm0 = fmaxf(rm0, fmaxf(s[ns][0], s[ns][1]));
            rm1 = fmaxf(rm1, fmaxf(s[ns][2], s[ns][3]));
        }
        rm0 = fmaxf(rm0, __shfl_xor_sync(0xFFFFFFFFu, rm0, 1));
        rm0 = fmaxf(rm0, __shfl_xor_sync(0xFFFFFFFFu, rm0, 2));
        rm1 = fmaxf(rm1, __shfl_xor_sync(0xFFFFFFFFu, rm1, 1));
        rm1 = fmaxf(rm1, __shfl_xor_sync(0xFFFFFFFFu, rm1, 2));

        const float nm0 = fmaxf(m0, rm0), nm1 = fmaxf(m1, rm1);
        const float a0 = __expf(m0 - nm0), a1 = __expf(m1 - nm1);
        float ps0 = 0.f, ps1 = 0.f;
        #pragma unroll
        for (int ns = 0; ns < 8; ns++) {
            s[ns][0] = __expf(s[ns][0] - nm0);
            s[ns][1] = __expf(s[ns][1] - nm0);
            s[ns][2] = __expf(s[ns][2] - nm1);
            s[ns][3] = __expf(s[ns][3] - nm1);
            ps0 += s[ns][0] + s[ns][1];
            ps1 += s[ns][2] + s[ns][3];
        }
        ps0 += __shfl_xor_sync(0xFFFFFFFFu, ps0, 1);
        ps0 += __shfl_xor_sync(0xFFFFFFFFu, ps0, 2);
        ps1 += __shfl_xor_sync(0xFFFFFFFFu, ps1, 1);
        ps1 += __shfl_xor_sync(0xFFFFFFFFu, ps1, 2);
        l0 = l0 * a0 + ps0;  m0 = nm0;
        l1 = l1 * a1 + ps1;  m1 = nm1;
        #pragma unroll
        for (int ns = 0; ns < 8; ns++) {
            o[ns][0] *= a0; o[ns][1] *= a0;
            o[ns][2] *= a1; o[ns][3] *= a1;
        }

        uint32_t pa[4][4];
        #pragma unroll
        for (int kk = 0; kk < 4; kk++) {
            pa[kk][0] = packh2(s[2 * kk][0],     s[2 * kk][1]);
            pa[kk][1] = packh2(s[2 * kk][2],     s[2 * kk][3]);
            pa[kk][2] = packh2(s[2 * kk + 1][0], s[2 * kk + 1][1]);
            pa[kk][3] = packh2(s[2 * kk + 1][2], s[2 * kk + 1][3]);
        }

        #pragma unroll
        for (int kk = 0; kk < 4; kk++) {
            #pragma unroll
            for (int ns = 0; ns < 8; ns++) {
                const uint32_t addr = sV_u[cur]
                    + (uint32_t)(((kk * 16 + (lane & 15)) * AT_STR + 8 * ns) * 2);
                uint32_t b0, b1;
                ldsm_x2_t(b0, b1, addr);
                mma_f16(o[ns], pa[kk], b0, b1);
            }
        }
        __syncthreads();
    }

    const float inv0 = 1.0f / l0;
    const float inv1 = 1.0f / l1;
    __half* ob0 = out + ((size_t)b * TN_ + qt * 128 + r_in0) * CN_ + headoff;
    __half* ob1 = out + ((size_t)b * TN_ + qt * 128 + r_in1) * CN_ + headoff;
    #pragma unroll
    for (int ns = 0; ns < 8; ns++) {
        const int d = 8 * ns + 2 * tq;
        *(__half2*)(ob0 + d) = __floats2half2_rn(o[ns][0] * inv0, o[ns][1] * inv0);
        *(__half2*)(ob1 + d) = __floats2half2_rn(o[ns][2] * inv1, o[ns][3] * inv1);
    }
}

// ---------------------------------------------------------------------------
// Launch
// ---------------------------------------------------------------------------
extern "C" void kernel_launch(void* const* d_in, const int* in_sizes, int n_in,
                              void* d_out, int out_size)
{
    const float* x    = (const float*)d_in[0];
    const float* ln1w = (const float*)d_in[2];
    const float* ln1b = (const float*)d_in[3];
    const float* ln2w = (const float*)d_in[4];
    const float* ln2b = (const float*)d_in[5];
    const float* wq   = (const float*)d_in[6];
    const float* bq   = (const float*)d_in[7];
    const float* wk   = (const float*)d_in[8];
    const float* bk   = (const float*)d_in[9];
    const float* wv   = (const float*)d_in[10];
    const float* bv   = (const float*)d_in[11];
    const float* wo   = (const float*)d_in[12];
    const float* bo   = (const float*)d_in[13];
    const float* w1   = (const float*)d_in[14];
    const float* b1   = (const float*)d_in[15];
    const float* w2   = (const float*)d_in[16];
    const float* b2   = (const float*)d_in[17];
    float* out = (float*)d_out;

    __half *h, *q, *k, *v, *ctx, *h2, *ff;
    float *x1;
    __half *wqt, *wkt, *wvt, *wot, *w1t, *w2t;
    cudaGetSymbolAddress((void**)&h,   g_h);
    cudaGetSymbolAddress((void**)&q,   g_q);
    cudaGetSymbolAddress((void**)&k,   g_k);
    cudaGetSymbolAddress((void**)&v,   g_v);
    cudaGetSymbolAddress((void**)&ctx, g_ctx);
    cudaGetSymbolAddress((void**)&x1,  g_x1);
    cudaGetSymbolAddress((void**)&h2,  g_h2);
    cudaGetSymbolAddress((void**)&ff,  g_ff);
    cudaGetSymbolAddress((void**)&wqt, g_wqt);
    cudaGetSymbolAddress((void**)&wkt, g_wkt);
    cudaGetSymbolAddress((void**)&wvt, g_wvt);
    cudaGetSymbolAddress((void**)&wot, g_wot);
    cudaGetSymbolAddress((void**)&w1t, g_w1t);
    cudaGetSymbolAddress((void**)&w2t, g_w2t);

    cudaFuncSetAttribute(gemm_h, cudaFuncAttributeMaxDynamicSharedMemorySize,
                         SMEM_GEMM_BYTES);
    cudaFuncSetAttribute(attn_tc, cudaFuncAttributeMaxDynamicSharedMemorySize,
                         SMEM_ATTN_BYTES);

    const dim3 blk(256);
    const dim3 tblk(32, 8);

    // 0. Transpose + convert weights to half (64-k tiles, half2 stores)
    convt<<<dim3(CN_ / 32, CN_ / 64, 4), tblk>>>(wq, wk, wv, wo,
                                                 wqt, wkt, wvt, wot, CN_, CN_);
    convt<<<dim3(FFD_ / 32, CN_ / 64, 1), tblk>>>(w1, w1, w1, w1,
                                                  w1t, w1t, w1t, w1t, CN_, FFD_);
    convt<<<dim3(CN_ / 32, FFD_ / 64, 1), tblk>>>(w2, w2, w2, w2,
                                                  w2t, w2t, w2t, w2t, FFD_, CN_);

    // 1. LN1 -> half (warp-per-row)
    ln_kernel<<<MD_ / 8, blk>>>(x, ln1w, ln1b, h);

    // 2. QKV projections merged (z=3) -> half
    const dim3 gQKV(CN_ / 128, MD_ / 128, 3);
    gemm_h<<<gQKV, blk, SMEM_GEMM_BYTES>>>(h, wqt, wkt, wvt, bq, bk, bv,
                                           q, k, v, nullptr, nullptr,
                                           MD_, CN_, CN_, 0);

    // 3. Causal flash attention -> ctx half (LPT block order)
    const dim3 gA(TN_ / 128, BN_ * HN_);
    attn_tc<<<gA, blk, SMEM_ATTN_BYTES>>>(q, k, v, ctx);

    // 4. Output projection + residual -> x1 fp32
    const dim3 gP(CN_ / 128, MD_ / 128, 1);
    gemm_h<<<gP, blk, SMEM_GEMM_BYTES>>>(ctx, wot, wot, wot, bo, bo, bo,
                                         nullptr, nullptr, nullptr, x1, x,
                                         MD_, CN_, CN_, 0);

    // 5. LN2 -> half (warp-per-row)
    ln_kernel<<<MD_ / 8, blk>>>(x1, ln2w, ln2b, h2);

    // 6. FFN
    const dim3 gF1(FFD_ / 128, MD_ / 128, 1);
    gemm_h<<<gF1, blk, SMEM_GEMM_BYTES>>>(h2, w1t, w1t, w1t, b1, b1, b1,
                                          ff, ff, ff, nullptr, nullptr,
                                          MD_, FFD_, CN_, 1);
    gemm_h<<<gP, blk, SMEM_GEMM_BYTES>>>(ff, w2t, w2t, w2t, b2, b2, b2,
                                         nullptr, nullptr, nullptr, out, x1,
                                         MD_, CN_, FFD_, 0);
}

// round 17
// speedup vs baseline: 1.0238x; 1.0238x over previous
#include <cuda_runtime.h>
#include <cuda_fp16.h>
#include <math.h>
#include <stdint.h>

// Problem constants
#define BN_ 8
#define TN_ 1024
#define CN_ 1024
#define HN_ 16
#define DH_ 64
#define MD_ (BN_ * TN_)      // 8192 rows
#define FFD_ (4 * CN_)       // 4096

// ---------------------------------------------------------------------------
// Scratch (device globals — no allocation allowed)
// ---------------------------------------------------------------------------
__device__ __half g_h  [MD_ * CN_];
__device__ __half g_q  [MD_ * CN_];
__device__ __half g_k  [MD_ * CN_];
__device__ __half g_v  [MD_ * CN_];
__device__ __half g_ctx[MD_ * CN_];
__device__ float  g_x1 [MD_ * CN_];
__device__ __half g_h2 [MD_ * CN_];
__device__ __half g_ff [MD_ * FFD_];
// transposed half weights: Wt[n][k] = W[k][n]
__device__ __half g_wqt[CN_ * CN_];
__device__ __half g_wkt[CN_ * CN_];
__device__ __half g_wvt[CN_ * CN_];
__device__ __half g_wot[CN_ * CN_];
__device__ __half g_w1t[FFD_ * CN_];
__device__ __half g_w2t[CN_ * FFD_];

// ---------------------------------------------------------------------------
// Helpers
// ---------------------------------------------------------------------------
__device__ __forceinline__ uint32_t smem_u32(const void* p) {
    uint32_t a;
    asm("{ .reg .u64 t; cvta.to.shared.u64 t, %1; cvt.u32.u64 %0, t; }" : "=r"(a) : "l"(p));
    return a;
}
__device__ __forceinline__ void cp_async16(uint32_t dst, const void* src) {
    asm volatile("cp.async.cg.shared.global [%0], [%1], 16;" :: "r"(dst), "l"(src));
}
__device__ __forceinline__ void cp_commit() {
    asm volatile("cp.async.commit_group;" ::: "memory");
}
__device__ __forceinline__ void cp_wait0() {
    asm volatile("cp.async.wait_group 0;" ::: "memory");
}
__device__ __forceinline__ void cp_wait1() {
    asm volatile("cp.async.wait_group 1;" ::: "memory");
}

__device__ __forceinline__ void mma_f16(float* d, const uint32_t* a,
                                        uint32_t b0, uint32_t b1)
{
    asm volatile(
        "mma.sync.aligned.m16n8k16.row.col.f32.f16.f16.f32 "
        "{%0,%1,%2,%3}, {%4,%5,%6,%7}, {%8,%9}, {%0,%1,%2,%3};"
        : "+f"(d[0]), "+f"(d[1]), "+f"(d[2]), "+f"(d[3])
        : "r"(a[0]), "r"(a[1]), "r"(a[2]), "r"(a[3]), "r"(b0), "r"(b1));
}
__device__ __forceinline__ void ldsm_x4(uint32_t* r, uint32_t addr)
{
    asm volatile("ldmatrix.sync.aligned.m8n8.x4.shared.b16 {%0,%1,%2,%3}, [%4];"
                 : "=r"(r[0]), "=r"(r[1]), "=r"(r[2]), "=r"(r[3]) : "r"(addr));
}
__device__ __forceinline__ void ldsm_x2_t(uint32_t& r0, uint32_t& r1, uint32_t addr)
{
    asm volatile("ldmatrix.sync.aligned.m8n8.x2.trans.shared.b16 {%0,%1}, [%2];"
                 : "=r"(r0), "=r"(r1) : "r"(addr));
}
__device__ __forceinline__ uint32_t packh2(float a, float b)
{
    const __half2 h = __floats2half2_rn(a, b);
    return *reinterpret_cast<const uint32_t*>(&h);
}

__device__ __forceinline__ float gelu_exact(float x)
{
    return 0.5f * x * (1.0f + erff(x * 0.70710678118654752f));
}

// ---------------------------------------------------------------------------
// Transpose + convert: Wt[n][k] = half(W[k][n]).
// Tile 64(k) x 32(n); block 32x8. Stores are half2 (aligned 4B per lane).
// ---------------------------------------------------------------------------
__global__ __launch_bounds__(256)
void convt(const float* W0, const float* W1, const float* W2, const float* W3,
           __half* T0, __half* T1, __half* T2, __half* T3, int K, int N)
{
    const int z = blockIdx.z;
    const float* W = (z == 0) ? W0 : (z == 1) ? W1 : (z == 2) ? W2 : W3;
    __half*      T = (z == 0) ? T0 : (z == 1) ? T1 : (z == 2) ? T2 : T3;

    __shared__ float tile[64][33];
    const int tx = threadIdx.x, ty = threadIdx.y;
    const int n0 = blockIdx.x * 32, k0 = blockIdx.y * 64;
    #pragma unroll
    for (int j = 0; j < 64; j += 8)
        tile[ty + j][tx] = W[(size_t)(k0 + ty + j) * N + n0 + tx];
    __syncthreads();
    #pragma unroll
    for (int j = 0; j < 32; j += 8) {
        const int n = n0 + ty + j;
        const __half2 hv = __floats2half2_rn(tile[2 * tx][ty + j],
                                             tile[2 * tx + 1][ty + j]);
        *(__half2*)(T + (size_t)n * K + k0 + 2 * tx) = hv;
    }
}

// ---------------------------------------------------------------------------
// FP16 tensor-core GEMM (R8 known-good): C = A@W + bias (+gelu)(+res).
// 128x128 tile, BK=32, 256 threads (8 warps 4x2, warp tile 32x64).
// 3-stage cp.async pipeline. ldmatrix.x4 fragments, stride 40 halves.
// ---------------------------------------------------------------------------
#define SG_STR 40
#define SG_TILE (128 * SG_STR)
#define SMEM_GEMM_BYTES (3 * 2 * SG_TILE * 2)  // 61440 B

__global__ __launch_bounds__(256, 2)
void gemm_h(const __half* __restrict__ A,
            const __half* T0, const __half* T1, const __half* T2,
            const float* b0p, const float* b1p, const float* b2p,
            __half* h0p, __half* h1p, __half* h2p,
            float* of, const float* __restrict__ res,
            int M, int N, int K, int act)
{
    const int z = blockIdx.z;
    const __half* Wt   = (z == 0) ? T0  : (z == 1) ? T1  : T2;
    const float*  bias = (z == 0) ? b0p : (z == 1) ? b1p : b2p;
    __half*       Ch   = (z == 0) ? h0p : (z == 1) ? h1p : h2p;

    extern __shared__ __half smh[];
    __half* sA0 = smh;
    const uint32_t sA_u[3] = { smem_u32(sA0),
                               smem_u32(sA0 + 2 * SG_TILE),
                               smem_u32(sA0 + 4 * SG_TILE) };
    const uint32_t sB_u[3] = { smem_u32(sA0 + SG_TILE),
                               smem_u32(sA0 + 3 * SG_TILE),
                               smem_u32(sA0 + 5 * SG_TILE) };

    const int tid  = threadIdx.x;
    const int wid  = tid >> 5;
    const int lane = tid & 31;
    const int g    = lane >> 2;
    const int tq   = lane & 3;
    const int bm = blockIdx.y * 128;
    const int bn = blockIdx.x * 128;
    const int wm = (wid & 3) * 32;
    const int wn = (wid >> 2) * 64;

    const uint32_t offA0 = (uint32_t)(((wm + (lane & 15)) * SG_STR + (lane >> 4) * 8) * 2);
    const uint32_t offA1 = offA0 + 16u * SG_STR * 2u;
    const int rB = (lane & 7) + ((lane >> 4) & 1) * 8;
    const uint32_t cBo = (uint32_t)(((lane >> 3) & 1) * 8);
    uint32_t offB[4];
    #pragma unroll
    for (int n2 = 0; n2 < 4; n2++)
        offB[n2] = (uint32_t)(((wn + n2 * 16 + rB) * SG_STR + cBo) * 2);

    float acc[2][8][4];
    #pragma unroll
    for (int ms = 0; ms < 2; ms++)
        #pragma unroll
        for (int ns = 0; ns < 8; ns++)
            #pragma unroll
            for (int i = 0; i < 4; i++) acc[ms][ns][i] = 0.f;

    const int nChunks = K >> 5;

    auto loadAB = [&](int c, int b) {
        const __half* Ab = A + (size_t)bm * K + (c << 5);
        const __half* Bb = Wt + (size_t)bn * K + (c << 5);
        #pragma unroll
        for (int it = 0; it < 2; ++it) {
            const int idx = tid + it * 256;
            const int row = idx >> 2;
            const int seg = idx & 3;
            cp_async16(sA_u[b] + (uint32_t)(row * SG_STR * 2 + seg * 16),
                       Ab + (size_t)row * K + seg * 8);
            cp_async16(sB_u[b] + (uint32_t)(row * SG_STR * 2 + seg * 16),
                       Bb + (size_t)row * K + seg * 8);
        }
    };

    auto compute = [&](int b) {
        const uint32_t bA = sA_u[b];
        const uint32_t bB = sB_u[b];
        #pragma unroll
        for (int kk = 0; kk < 2; kk++) {
            const uint32_t ko = (uint32_t)(kk * 32);
            uint32_t a[2][4];
            ldsm_x4(a[0], bA + offA0 + ko);
            ldsm_x4(a[1], bA + offA1 + ko);
            #pragma unroll
            for (int n2 = 0; n2 < 4; n2++) {
                uint32_t bb[4];
                ldsm_x4(bb, bB + offB[n2] + ko);
                mma_f16(acc[0][2 * n2],     a[0], bb[0], bb[1]);
                mma_f16(acc[1][2 * n2],     a[1], bb[0], bb[1]);
                mma_f16(acc[0][2 * n2 + 1], a[0], bb[2], bb[3]);
                mma_f16(acc[1][2 * n2 + 1], a[1], bb[2], bb[3]);
            }
        }
    };

    loadAB(0, 0); cp_commit();
    if (nChunks > 1) { loadAB(1, 1); cp_commit(); }

    for (int c = 0; c < nChunks; ++c) {
        if (c + 1 < nChunks) cp_wait1(); else cp_wait0();
        __syncthreads();
        compute(c % 3);
        if (c + 2 < nChunks) { loadAB(c + 2, (c + 2) % 3); cp_commit(); }
    }

    #pragma unroll
    for (int ms = 0; ms < 2; ms++) {
        const int r0 = bm + wm + 16 * ms + g;
        const int r1 = r0 + 8;
        #pragma unroll
        for (int ns = 0; ns < 8; ns++) {
            const int col = bn + wn + 8 * ns + 2 * tq;
            const float2 bb = *(const float2*)(bias + col);
            float o00 = acc[ms][ns][0] + bb.x;
            float o01 = acc[ms][ns][1] + bb.y;
            float o10 = acc[ms][ns][2] + bb.x;
            float o11 = acc[ms][ns][3] + bb.y;
            if (act) {
                o00 = gelu_exact(o00); o01 = gelu_exact(o01);
                o10 = gelu_exact(o10); o11 = gelu_exact(o11);
            }
            if (of) {
                if (res) {
                    const float2 q0 = *(const float2*)(res + (size_t)r0 * N + col);
                    const float2 q1 = *(const float2*)(res + (size_t)r1 * N + col);
                    o00 += q0.x; o01 += q0.y; o10 += q1.x; o11 += q1.y;
                }
                *(float2*)(of + (size_t)r0 * N + col) = make_float2(o00, o01);
                *(float2*)(of + (size_t)r1 * N + col) = make_float2(o10, o11);
            } else {
                *(__half2*)(Ch + (size_t)r0 * N + col) = __floats2half2_rn(o00, o01);
                *(__half2*)(Ch + (size_t)r1 * N + col) = __floats2half2_rn(o10, o11);
            }
        }
    }
}

// ---------------------------------------------------------------------------
// LayerNorm: warp handles 2 rows (16 rows/block, grid 512). No smem/barrier.
// ---------------------------------------------------------------------------
__global__ __launch_bounds__(256)
void ln_kernel(const float* __restrict__ x, const float* __restrict__ w,
               const float* __restrict__ b, __half* __restrict__ out)
{
    const int wid  = threadIdx.x >> 5;
    const int lane = threadIdx.x & 31;
    const int row0 = blockIdx.x * 16 + wid * 2;

    const float* xr0 = x + (size_t)row0 * CN_;
    const float* xr1 = xr0 + CN_;
    float4 v0[8], v1[8];
    float s0 = 0.f, ss0 = 0.f, s1 = 0.f, ss1 = 0.f;
    #pragma unroll
    for (int i = 0; i < 8; i++) {
        v0[i] = *(const float4*)(xr0 + (i * 32 + lane) * 4);
        v1[i] = *(const float4*)(xr1 + (i * 32 + lane) * 4);
    }
    #pragma unroll
    for (int i = 0; i < 8; i++) {
        s0  += v0[i].x + v0[i].y + v0[i].z + v0[i].w;
        ss0 += v0[i].x * v0[i].x + v0[i].y * v0[i].y
             + v0[i].z * v0[i].z + v0[i].w * v0[i].w;
        s1  += v1[i].x + v1[i].y + v1[i].z + v1[i].w;
        ss1 += v1[i].x * v1[i].x + v1[i].y * v1[i].y
             + v1[i].z * v1[i].z + v1[i].w * v1[i].w;
    }
    #pragma unroll
    for (int o = 16; o > 0; o >>= 1) {
        s0  += __shfl_xor_sync(0xFFFFFFFFu, s0,  o);
        ss0 += __shfl_xor_sync(0xFFFFFFFFu, ss0, o);
        s1  += __shfl_xor_sync(0xFFFFFFFFu, s1,  o);
        ss1 += __shfl_xor_sync(0xFFFFFFFFu, ss1, o);
    }

    const float mu0   = s0 * (1.0f / (float)CN_);
    const float var0  = ss0 * (1.0f / (float)CN_) - mu0 * mu0;
    const float rs0   = rsqrtf(var0 + 1e-5f);
    const float mu1   = s1 * (1.0f / (float)CN_);
    const float var1  = ss1 * (1.0f / (float)CN_) - mu1 * mu1;
    const float rs1   = rsqrtf(var1 + 1e-5f);

    __half* o0r = out + (size_t)row0 * CN_;
    __half* o1r = o0r + CN_;
    #pragma unroll
    for (int i = 0; i < 8; i++) {
        const int c = (i * 32 + lane) * 4;
        const float4 wv = *(const float4*)(w + c);
        const float4 bv = *(const float4*)(b + c);
        {
            const float a0 = (v0[i].x - mu0) * rs0 * wv.x + bv.x;
            const float a1 = (v0[i].y - mu0) * rs0 * wv.y + bv.y;
            const float a2 = (v0[i].z - mu0) * rs0 * wv.z + bv.z;
            const float a3 = (v0[i].w - mu0) * rs0 * wv.w + bv.w;
            __half2 h01 = __floats2half2_rn(a0, a1);
            __half2 h23 = __floats2half2_rn(a2, a3);
            uint2 pk;
            pk.x = *reinterpret_cast<uint32_t*>(&h01);
            pk.y = *reinterpret_cast<uint32_t*>(&h23);
            *(uint2*)(o0r + c) = pk;
        }
        {
            const float a0 = (v1[i].x - mu1) * rs1 * wv.x + bv.x;
            const float a1 = (v1[i].y - mu1) * rs1 * wv.y + bv.y;
            const float a2 = (v1[i].z - mu1) * rs1 * wv.z + bv.z;
            const float a3 = (v1[i].w - mu1) * rs1 * wv.w + bv.w;
            __half2 h01 = __floats2half2_rn(a0, a1);
            __half2 h23 = __floats2half2_rn(a2, a3);
            uint2 pk;
            pk.x = *reinterpret_cast<uint32_t*>(&h01);
            pk.y = *reinterpret_cast<uint32_t*>(&h23);
            *(uint2*)(o1r + c) = pk;
        }
    }
}

// ---------------------------------------------------------------------------
// FP16 flash attention (causal). Block 256 threads (8 warps); q-tile 128,
// kv-tile 64, d=64. Q frags in regs; P in registers.
// GLOBAL LPT: 1-D grid 1024; qt = 7 - (bid>>7), bh = bid & 127.
// ---------------------------------------------------------------------------
#define AT_STR 72
#define AQ_TILE (128 * AT_STR)
#define AKV_TILE (64 * AT_STR)
#define SMEM_ATTN_BYTES ((AQ_TILE + 4 * AKV_TILE) * 2)   // 55296 B

__global__ __launch_bounds__(256, 2)
void attn_tc(const __half* __restrict__ q, const __half* __restrict__ k,
             const __half* __restrict__ v, __half* __restrict__ out)
{
    extern __shared__ __half smh[];
    __half* sQ = smh;
    const uint32_t sQ_u    = smem_u32(sQ);
    const uint32_t sK_u[2] = { smem_u32(smh + AQ_TILE),
                               smem_u32(smh + AQ_TILE + 2 * AKV_TILE) };
    const uint32_t sV_u[2] = { smem_u32(smh + AQ_TILE + AKV_TILE),
                               smem_u32(smh + AQ_TILE + 3 * AKV_TILE) };

    const int bid = blockIdx.x;
    const int qt  = 7 - (bid >> 7);       // global LPT: heaviest first
    const int bh  = bid & 127;
    const int b   = bh >> 4;
    const int h   = bh & 15;
    const int tid  = threadIdx.x;
    const int wid  = tid >> 5;
    const int lane = tid & 31;
    const int g    = lane >> 2;
    const int tq   = lane & 3;

    const size_t headoff = (size_t)h * DH_;
    const __half* qbase = q + ((size_t)b * TN_ + qt * 128) * CN_ + headoff;

    #pragma unroll
    for (int it = 0; it < 4; ++it) {
        const int idx = tid + it * 256;
        const int row = idx >> 3;
        const int seg = idx & 7;
        cp_async16(sQ_u + (uint32_t)(row * AT_STR * 2 + seg * 16),
                   qbase + (size_t)row * CN_ + seg * 8);
    }
    auto loadKV = [&](int kt, int bb) {
        const __half* kb = k + ((size_t)b * TN_ + kt * 64) * CN_ + headoff;
        const __half* vb = v + ((size_t)b * TN_ + kt * 64) * CN_ + headoff;
        #pragma unroll
        for (int it = 0; it < 2; ++it) {
            const int idx = tid + it * 256;
            const int row = idx >> 3;
            const int seg = idx & 7;
            cp_async16(sK_u[bb] + (uint32_t)(row * AT_STR * 2 + seg * 16),
                       kb + (size_t)row * CN_ + seg * 8);
            cp_async16(sV_u[bb] + (uint32_t)(row * AT_STR * 2 + seg * 16),
                       vb + (size_t)row * CN_ + seg * 8);
        }
    };

    loadKV(0, 0);
    cp_commit();
    cp_wait0();
    __syncthreads();

    const int r_in0 = 16 * wid + g;
    const int r_in1 = r_in0 + 8;
    const int rowg0 = qt * 128 + r_in0;
    const int rowg1 = rowg0 + 8;

    const int rB = (lane & 7) + ((lane >> 4) & 1) * 8;
    const uint32_t cBo = (uint32_t)(((lane >> 3) & 1) * 8);
    uint32_t offK[4];
    #pragma unroll
    for (int n2 = 0; n2 < 4; n2++)
        offK[n2] = (uint32_t)(((n2 * 16 + rB) * AT_STR + cBo) * 2);

    uint32_t qa[4][4];
    {
        const __half2 sc = __float2half2_rn(0.125f);
        #pragma unroll
        for (int kk = 0; kk < 4; kk++) {
            const int kb = kk * 16 + 2 * tq;
            #pragma unroll
            for (int i = 0; i < 4; i++) {
                const int rr = (i & 1) ? r_in1 : r_in0;
                const int cc = kb + ((i >> 1) ? 8 : 0);
                uint32_t raw = *(const uint32_t*)(sQ + rr * AT_STR + cc);
                __half2 hv = *reinterpret_cast<__half2*>(&raw);
                hv = __hmul2(hv, sc);
                qa[kk][i] = *reinterpret_cast<uint32_t*>(&hv);
            }
        }
    }

    float o[8][4];
    #pragma unroll
    for (int ns = 0; ns < 8; ns++)
        #pragma unroll
        for (int i = 0; i < 4; i++) o[ns][i] = 0.f;
    float m0 = -1e30f, m1 = -1e30f, l0 = 0.f, l1 = 0.f;

    const int ktMax = 2 * qt + 1;

    for (int kt = 0; kt <= ktMax; kt++) {
        const int cur = kt & 1;
        if (kt + 1 <= ktMax) { loadKV(kt + 1, cur ^ 1); cp_commit(); }
        if (kt + 1 <= ktMax) cp_wait1(); else cp_wait0();
        __syncthreads();

        float s[8][4];
        #pragma unroll
        for (int ns = 0; ns < 8; ns++)
            #pragma unroll
            for (int i = 0; i < 4; i++) s[ns][i] = 0.f;
        #pragma unroll
        for (int kk = 0; kk < 4; kk++) {
            const uint32_t ko = (uint32_t)(kk * 32);
            #pragma unroll
            for (int n2 = 0; n2 < 4; n2++) {
                uint32_t bb[4];
                ldsm_x4(bb, sK_u[cur] + offK[n2] + ko);
                mma_f16(s[2 * n2],     qa[kk], bb[0], bb[1]);
                mma_f16(s[2 * n2 + 1], qa[kk], bb[2], bb[3]);
            }
        }

        if (kt >= 2 * qt) {
            const int colbase = kt * 64;
            #pragma unroll
            for (int ns = 0; ns < 8; ns++) {
                const int c0 = colbase + 8 * ns + 2 * tq;
                if (c0     > rowg0) s[ns][0] = -1e30f;
                if (c0 + 1 > rowg0) s[ns][1] = -1e30f;
                if (c0     > rowg1) s[ns][2] = -1e30f;
                if (c0 + 1 > rowg1) s[ns][3] = -1e30f;
            }
        }

        float rm0 = -1e30f, rm1 = -1e30f;
        #pragma unroll
        for (int ns = 0; ns < 8; ns++) {
            rm0 = fmaxf(rm0, fmaxf(s[ns][0], s[ns][1]));
            rm1 = fmaxf(rm1, fmaxf(s[ns][2], s[ns][3]));
        }
        rm0 = fmaxf(rm0, __shfl_xor_sync(0xFFFFFFFFu, rm0, 1));
        rm0 = fmaxf(rm0, __shfl_xor_sync(0xFFFFFFFFu, rm0, 2));
        rm1 = fmaxf(rm1, __shfl_xor_sync(0xFFFFFFFFu, rm1, 1));
        rm1 = fmaxf(rm1, __shfl_xor_sync(0xFFFFFFFFu, rm1, 2));

        const float nm0 = fmaxf(m0, rm0), nm1 = fmaxf(m1, rm1);
        const float a0 = __expf(m0 - nm0), a1 = __expf(m1 - nm1);
        float ps0 = 0.f, ps1 = 0.f;
        #pragma unroll
        for (int ns = 0; ns < 8; ns++) {
            s[ns][0] = __expf(s[ns][0] - nm0);
            s[ns][1] = __expf(s[ns][1] - nm0);
            s[ns][2] = __expf(s[ns][2] - nm1);
            s[ns][3] = __expf(s[ns][3] - nm1);
            ps0 += s[ns][0] + s[ns][1];
            ps1 += s[ns][2] + s[ns][3];
        }
        ps0 += __shfl_xor_sync(0xFFFFFFFFu, ps0, 1);
        ps0 += __shfl_xor_sync(0xFFFFFFFFu, ps0, 2);
        ps1 += __shfl_xor_sync(0xFFFFFFFFu, ps1, 1);
        ps1 += __shfl_xor_sync(0xFFFFFFFFu, ps1, 2);
        l0 = l0 * a0 + ps0;  m0 = nm0;
        l1 = l1 * a1 + ps1;  m1 = nm1;
        #pragma unroll
        for (int ns = 0; ns < 8; ns++) {
            o[ns][0] *= a0; o[ns][1] *= a0;
            o[ns][2] *= a1; o[ns][3] *= a1;
        }

        uint32_t pa[4][4];
        #pragma unroll
        for (int kk = 0; kk < 4; kk++) {
            pa[kk][0] = packh2(s[2 * kk][0],     s[2 * kk][1]);
            pa[kk][1] = packh2(s[2 * kk][2],     s[2 * kk][3]);
            pa[kk][2] = packh2(s[2 * kk + 1][0], s[2 * kk + 1][1]);
            pa[kk][3] = packh2(s[2 * kk + 1][2], s[2 * kk + 1][3]);
        }

        #pragma unroll
        for (int kk = 0; kk < 4; kk++) {
            #pragma unroll
            for (int ns = 0; ns < 8; ns++) {
                const uint32_t addr = sV_u[cur]
                    + (uint32_t)(((kk * 16 + (lane & 15)) * AT_STR + 8 * ns) * 2);
                uint32_t b0, b1;
                ldsm_x2_t(b0, b1, addr);
                mma_f16(o[ns], pa[kk], b0, b1);
            }
        }
        __syncthreads();
    }

    const float inv0 = 1.0f / l0;
    const float inv1 = 1.0f / l1;
    __half* ob0 = out + ((size_t)b * TN_ + qt * 128 + r_in0) * CN_ + headoff;
    __half* ob1 = out + ((size_t)b * TN_ + qt * 128 + r_in1) * CN_ + headoff;
    #pragma unroll
    for (int ns = 0; ns < 8; ns++) {
        const int d = 8 * ns + 2 * tq;
        *(__half2*)(ob0 + d) = __floats2half2_rn(o[ns][0] * inv0, o[ns][1] * inv0);
        *(__half2*)(ob1 + d) = __floats2half2_rn(o[ns][2] * inv1, o[ns][3] * inv1);
    }
}

// ---------------------------------------------------------------------------
// Launch
// ---------------------------------------------------------------------------
extern "C" void kernel_launch(void* const* d_in, const int* in_sizes, int n_in,
                              void* d_out, int out_size)
{
    const float* x    = (const float*)d_in[0];
    const float* ln1w = (const float*)d_in[2];
    const float* ln1b = (const float*)d_in[3];
    const float* ln2w = (const float*)d_in[4];
    const float* ln2b = (const float*)d_in[5];
    const float* wq   = (const float*)d_in[6];
    const float* bq   = (const float*)d_in[7];
    const float* wk   = (const float*)d_in[8];
    const float* bk   = (const float*)d_in[9];
    const float* wv   = (const float*)d_in[10];
    const float* bv   = (const float*)d_in[11];
    const float* wo   = (const float*)d_in[12];
    const float* bo   = (const float*)d_in[13];
    const float* w1   = (const float*)d_in[14];
    const float* b1   = (const float*)d_in[15];
    const float* w2   = (const float*)d_in[16];
    const float* b2   = (const float*)d_in[17];
    float* out = (float*)d_out;

    __half *h, *q, *k, *v, *ctx, *h2, *ff;
    float *x1;
    __half *wqt, *wkt, *wvt, *wot, *w1t, *w2t;
    cudaGetSymbolAddress((void**)&h,   g_h);
    cudaGetSymbolAddress((void**)&q,   g_q);
    cudaGetSymbolAddress((void**)&k,   g_k);
    cudaGetSymbolAddress((void**)&v,   g_v);
    cudaGetSymbolAddress((void**)&ctx, g_ctx);
    cudaGetSymbolAddress((void**)&x1,  g_x1);
    cudaGetSymbolAddress((void**)&h2,  g_h2);
    cudaGetSymbolAddress((void**)&ff,  g_ff);
    cudaGetSymbolAddress((void**)&wqt, g_wqt);
    cudaGetSymbolAddress((void**)&wkt, g_wkt);
    cudaGetSymbolAddress((void**)&wvt, g_wvt);
    cudaGetSymbolAddress((void**)&wot, g_wot);
    cudaGetSymbolAddress((void**)&w1t, g_w1t);
    cudaGetSymbolAddress((void**)&w2t, g_w2t);

    cudaFuncSetAttribute(gemm_h, cudaFuncAttributeMaxDynamicSharedMemorySize,
                         SMEM_GEMM_BYTES);
    cudaFuncSetAttribute(attn_tc, cudaFuncAttributeMaxDynamicSharedMemorySize,
                         SMEM_ATTN_BYTES);

    const dim3 blk(256);
    const dim3 tblk(32, 8);

    // 0. Transpose + convert weights to half (64-k tiles, half2 stores)
    convt<<<dim3(CN_ / 32, CN_ / 64, 4), tblk>>>(wq, wk, wv, wo,
                                                 wqt, wkt, wvt, wot, CN_, CN_);
    convt<<<dim3(FFD_ / 32, CN_ / 64, 1), tblk>>>(w1, w1, w1, w1,
                                                  w1t, w1t, w1t, w1t, CN_, FFD_);
    convt<<<dim3(CN_ / 32, FFD_ / 64, 1), tblk>>>(w2, w2, w2, w2,
                                                  w2t, w2t, w2t, w2t, FFD_, CN_);

    // 1. LN1 -> half (2 rows per warp)
    ln_kernel<<<MD_ / 16, blk>>>(x, ln1w, ln1b, h);

    // 2. QKV projections merged (z=3) -> half
    const dim3 gQKV(CN_ / 128, MD_ / 128, 3);
    gemm_h<<<gQKV, blk, SMEM_GEMM_BYTES>>>(h, wqt, wkt, wvt, bq, bk, bv,
                                           q, k, v, nullptr, nullptr,
                                           MD_, CN_, CN_, 0);

    // 3. Causal flash attention -> ctx half (global LPT, 1-D grid)
    attn_tc<<<TN_ / 128 * BN_ * HN_, blk, SMEM_ATTN_BYTES>>>(q, k, v, ctx);

    // 4. Output projection + residual -> x1 fp32
    const dim3 gP(CN_ / 128, MD_ / 128, 1);
    gemm_h<<<gP, blk, SMEM_GEMM_BYTES>>>(ctx, wot, wot, wot, bo, bo, bo,
                                         nullptr, nullptr, nullptr, x1, x,
                                         MD_, CN_, CN_, 0);

    // 5. LN2 -> half (2 rows per warp)
    ln_kernel<<<MD_ / 16, blk>>>(x1, ln2w, ln2b, h2);

    // 6. FFN
    const dim3 gF1(FFD_ / 128, MD_ / 128, 1);
    gemm_h<<<gF1, blk, SMEM_GEMM_BYTES>>>(h2, w1t, w1t, w1t, b1, b1, b1,
                                          ff, ff, ff, nullptr, nullptr,
                                          MD_, FFD_, CN_, 1);
    gemm_h<<<gP, blk, SMEM_GEMM_BYTES>>>(ff, w2t, w2t, w2t, b2, b2, b2,
                                         nullptr, nullptr, nullptr, out, x1,
                                         MD_, CN_, FFD_, 0);
}